// round 14
// baseline (speedup 1.0000x reference)
#include <cuda_runtime.h>
#include <cuda_fp16.h>
#include <cstdint>

#define NN 50000
#define EE 800000
#define HC 128
#define INF 256
#define CAP 64            // bucket capacity per node (Poisson(17) tail @64 ~ 1e-16)

// ---------------- static device scratch ----------------
__device__ __align__(16) __half g_h16[(size_t)NN * HC];      // 12.8 MB (h, then h*invden)
__device__ __align__(16) float g_al[NN * 4];
__device__ __align__(16) float g_ar[NN * 4];
__device__ __align__(16) float g_denom[NN * 4];              // self-resetting
__device__ int   g_cnt[NN];                                  // self-resetting
__device__ __align__(16) uint4 g_bkt[(size_t)NN * CAP];      // {src, h2(e0,e1), h2(e2,e3), 0}

__device__ __forceinline__ float lrelu(float a) {
    return a > 0.0f ? a : 0.2f * a;
}
__device__ __forceinline__ uint32_t packh2(float a, float b) {
    __half2 h = __floats2half2_rn(a, b);
    return *(uint32_t*)&h;
}

// ---------------- 1. fp16 MMA GEMM (m16n8k16), ping-pong smem, 1 sync/tile ----------
#define GBM 128
#define GBK 32
#define ASTRIDE 20
#define BSTRIDE 136
__global__ __launch_bounds__(256, 2)
void mma_gemm_kernel(const float* __restrict__ X, const float* __restrict__ W,
                     const float* __restrict__ att, int n) {
    __shared__ uint32_t Ash[2][GBM * ASTRIDE];   // 2 x 10.2 KB
    __shared__ uint32_t Bsh[2][16 * BSTRIDE];    // 2 x 8.7 KB
    __shared__ float s_att[256];
    int t = threadIdx.x;
    int lane = t & 31, warp = t >> 5;
    int grp = lane >> 2;
    int tig = lane & 3;
    int wm = (warp & 3) * 32;
    int wn = (warp >> 2) * 64;
    int rowbase = blockIdx.x * GBM;

    if (t < 256) s_att[t] = att[t];

    float acc[2][8][4];
#pragma unroll
    for (int ms = 0; ms < 2; ms++)
#pragma unroll
        for (int ns = 0; ns < 8; ns++)
#pragma unroll
            for (int q = 0; q < 4; q++) acc[ms][ns][q] = 0.0f;

    const int a_row = t >> 3;
    const int a_kq  = (t & 7) * 4;
    const int kq2   = (t & 7) * 2;
    const int b_kk  = t >> 5;
    const int b_nq  = (t & 31) * 4;

    float4 av[4], bv0[2], bv1[2];
#pragma unroll
    for (int i = 0; i < 4; i++) {
        int gr = rowbase + a_row + i * 32;
        av[i] = (gr < n) ? *(const float4*)(X + (size_t)gr * INF + a_kq)
                         : make_float4(0.f, 0.f, 0.f, 0.f);
    }
#pragma unroll
    for (int i = 0; i < 2; i++) {
        int kk = b_kk + i * 8;
        bv0[i] = *(const float4*)(W + (size_t)(2 * kk)     * HC + b_nq);
        bv1[i] = *(const float4*)(W + (size_t)(2 * kk + 1) * HC + b_nq);
    }
    // store tile 0 into stage 0
#pragma unroll
    for (int i = 0; i < 4; i++) {
        int m = a_row + i * 32;
        uint2 p;
        p.x = packh2(av[i].x, av[i].y);
        p.y = packh2(av[i].z, av[i].w);
        *(uint2*)&Ash[0][m * ASTRIDE + kq2] = p;
    }
#pragma unroll
    for (int i = 0; i < 2; i++) {
        int kk = b_kk + i * 8;
        uint4 pk;
        pk.x = packh2(bv0[i].x, bv1[i].x);
        pk.y = packh2(bv0[i].y, bv1[i].y);
        pk.z = packh2(bv0[i].z, bv1[i].z);
        pk.w = packh2(bv0[i].w, bv1[i].w);
        *(uint4*)&Bsh[0][kk * BSTRIDE + b_nq] = pk;
    }
    __syncthreads();

#pragma unroll
    for (int kt = 0; kt < 8; kt++) {
        int stage = kt & 1;
        int kb = kt * GBK;
        // prefetch next tile into registers (overlaps MMA)
        if (kt < 7) {
#pragma unroll
            for (int i = 0; i < 4; i++) {
                int gr = rowbase + a_row + i * 32;
                av[i] = (gr < n) ? *(const float4*)(X + (size_t)gr * INF + kb + GBK + a_kq)
                                 : make_float4(0.f, 0.f, 0.f, 0.f);
            }
#pragma unroll
            for (int i = 0; i < 2; i++) {
                int kk = b_kk + i * 8;
                bv0[i] = *(const float4*)(W + (size_t)(kb + GBK + 2 * kk)     * HC + b_nq);
                bv1[i] = *(const float4*)(W + (size_t)(kb + GBK + 2 * kk + 1) * HC + b_nq);
            }
        }
        // compute from current stage
        const uint32_t* As = Ash[stage];
        const uint32_t* Bs = Bsh[stage];
#pragma unroll
        for (int c = 0; c < 2; c++) {
            int kkb = c * 8 + tig;
            uint32_t a[2][4];
#pragma unroll
            for (int ms = 0; ms < 2; ms++) {
                int r = wm + ms * 16 + grp;
                a[ms][0] = As[r * ASTRIDE + kkb];
                a[ms][1] = As[(r + 8) * ASTRIDE + kkb];
                a[ms][2] = As[r * ASTRIDE + kkb + 4];
                a[ms][3] = As[(r + 8) * ASTRIDE + kkb + 4];
            }
#pragma unroll
            for (int ns = 0; ns < 8; ns++) {
                int cidx = wn + ns * 8 + grp;
                uint32_t b0 = Bs[kkb * BSTRIDE + cidx];
                uint32_t b1 = Bs[(kkb + 4) * BSTRIDE + cidx];
#pragma unroll
                for (int ms = 0; ms < 2; ms++) {
                    asm volatile(
                        "mma.sync.aligned.m16n8k16.row.col.f32.f16.f16.f32 "
                        "{%0,%1,%2,%3}, {%4,%5,%6,%7}, {%8,%9}, {%0,%1,%2,%3};"
                        : "+f"(acc[ms][ns][0]), "+f"(acc[ms][ns][1]),
                          "+f"(acc[ms][ns][2]), "+f"(acc[ms][ns][3])
                        : "r"(a[ms][0]), "r"(a[ms][1]), "r"(a[ms][2]), "r"(a[ms][3]),
                          "r"(b0), "r"(b1));
                }
            }
        }
        // store next tile into the idle stage, single sync
        if (kt < 7) {
            uint32_t* An = Ash[stage ^ 1];
            uint32_t* Bn = Bsh[stage ^ 1];
#pragma unroll
            for (int i = 0; i < 4; i++) {
                int m = a_row + i * 32;
                uint2 p;
                p.x = packh2(av[i].x, av[i].y);
                p.y = packh2(av[i].z, av[i].w);
                *(uint2*)&An[m * ASTRIDE + kq2] = p;
            }
#pragma unroll
            for (int i = 0; i < 2; i++) {
                int kk = b_kk + i * 8;
                uint4 pk;
                pk.x = packh2(bv0[i].x, bv1[i].x);
                pk.y = packh2(bv0[i].y, bv1[i].y);
                pk.z = packh2(bv0[i].z, bv1[i].z);
                pk.w = packh2(bv0[i].w, bv1[i].w);
                *(uint4*)&Bn[kk * BSTRIDE + b_nq] = pk;
            }
            __syncthreads();
        }
    }

    // ---- store h fragments as fp16 ----
#pragma unroll
    for (int ms = 0; ms < 2; ms++) {
#pragma unroll
        for (int ns = 0; ns < 8; ns++) {
            int r = rowbase + wm + ms * 16 + grp;
            int c = wn + ns * 8 + tig * 2;
            if (r < n)
                *(__half2*)(g_h16 + (size_t)r * HC + c) =
                    __floats2half2_rn(acc[ms][ns][0], acc[ms][ns][1]);
            if (r + 8 < n)
                *(__half2*)(g_h16 + (size_t)(r + 8) * HC + c) =
                    __floats2half2_rn(acc[ms][ns][2], acc[ms][ns][3]);
        }
    }

    // ---- fused attention dots ----
    float pal[4][2], par[4][2];
#pragma unroll
    for (int i = 0; i < 4; i++) { pal[i][0]=pal[i][1]=par[i][0]=par[i][1]=0.f; }
#pragma unroll
    for (int ns = 0; ns < 8; ns++) {
        int hs = ns >> 2;
        int c = wn + ns * 8 + tig * 2;
        int hd = c >> 5;
        int ci = c & 31;
        float wl0 = s_att[hd * 64 + ci],      wl1 = s_att[hd * 64 + ci + 1];
        float wr0 = s_att[hd * 64 + 32 + ci], wr1 = s_att[hd * 64 + 32 + ci + 1];
#pragma unroll
        for (int ms = 0; ms < 2; ms++) {
            pal[ms*2+0][hs] += acc[ms][ns][0]*wl0 + acc[ms][ns][1]*wl1;
            par[ms*2+0][hs] += acc[ms][ns][0]*wr0 + acc[ms][ns][1]*wr1;
            pal[ms*2+1][hs] += acc[ms][ns][2]*wl0 + acc[ms][ns][3]*wl1;
            par[ms*2+1][hs] += acc[ms][ns][2]*wr0 + acc[ms][ns][3]*wr1;
        }
    }
#pragma unroll
    for (int i = 0; i < 4; i++)
#pragma unroll
        for (int hs = 0; hs < 2; hs++) {
            pal[i][hs] += __shfl_xor_sync(0xffffffffu, pal[i][hs], 1);
            pal[i][hs] += __shfl_xor_sync(0xffffffffu, pal[i][hs], 2);
            par[i][hs] += __shfl_xor_sync(0xffffffffu, par[i][hs], 1);
            par[i][hs] += __shfl_xor_sync(0xffffffffu, par[i][hs], 2);
        }
    if (tig == 0) {
        int headbase = wn >> 5;
#pragma unroll
        for (int i = 0; i < 4; i++) {
            int r = rowbase + wm + (i >> 1) * 16 + grp + (i & 1) * 8;
            if (r < n) {
#pragma unroll
                for (int hs = 0; hs < 2; hs++) {
                    g_al[r * 4 + headbase + hs] = pal[i][hs];
                    g_ar[r * 4 + headbase + hs] = par[i][hs];
                }
            }
        }
    }
}

// ---------------- 2. fused edge pass: 2 edges/thread for MLP on the atomic chain ----
__global__ void edge_kernel(const int* __restrict__ ei, int E, int Et, int halfT) {
    int t = blockIdx.x * blockDim.x + threadIdx.x;
    if (t >= halfT) return;
    int e0 = t, e1 = t + halfT;
    bool has1 = e1 < Et;

    int s0, d0, s1 = 0, d1 = 0;
    if (e0 < E) { s0 = __ldg(ei + e0); d0 = __ldg(ei + E + e0); }
    else        { s0 = d0 = e0 - E; }
    if (has1) {
        if (e1 < E) { s1 = __ldg(ei + e1); d1 = __ldg(ei + E + e1); }
        else        { s1 = d1 = e1 - E; }
    }

    // gathers for both edges issued back-to-back (independent)
    float4 alv0 = *(const float4*)(g_al + d0 * 4);
    float4 arv0 = *(const float4*)(g_ar + s0 * 4);
    float4 alv1, arv1;
    if (has1) {
        alv1 = *(const float4*)(g_al + d1 * 4);
        arv1 = *(const float4*)(g_ar + s1 * 4);
    }

    float a0 = __expf(lrelu(alv0.x + arv0.x));
    float a1 = __expf(lrelu(alv0.y + arv0.y));
    float a2 = __expf(lrelu(alv0.z + arv0.z));
    float a3 = __expf(lrelu(alv0.w + arv0.w));
    asm volatile("red.global.add.v4.f32 [%0], {%1,%2,%3,%4};"
                 :: "l"(g_denom + s0 * 4), "f"(a0), "f"(a1), "f"(a2), "f"(a3)
                 : "memory");
    float b0, b1, b2, b3;
    if (has1) {
        b0 = __expf(lrelu(alv1.x + arv1.x));
        b1 = __expf(lrelu(alv1.y + arv1.y));
        b2 = __expf(lrelu(alv1.z + arv1.z));
        b3 = __expf(lrelu(alv1.w + arv1.w));
        asm volatile("red.global.add.v4.f32 [%0], {%1,%2,%3,%4};"
                     :: "l"(g_denom + s1 * 4), "f"(b0), "f"(b1), "f"(b2), "f"(b3)
                     : "memory");
    }

    // two independent atomic chains
    int p0 = atomicAdd(&g_cnt[d0], 1);
    int p1 = has1 ? atomicAdd(&g_cnt[d1], 1) : CAP;
    if (p0 < CAP) {
        uint4 v;
        v.x = (uint32_t)s0;
        v.y = packh2(a0, a1);
        v.z = packh2(a2, a3);
        v.w = 0;
        g_bkt[(d0 << 6) + p0] = v;
    }
    if (has1 && p1 < CAP) {
        uint4 v;
        v.x = (uint32_t)s1;
        v.y = packh2(b0, b1);
        v.z = packh2(b2, b3);
        v.w = 0;
        g_bkt[(d1 << 6) + p1] = v;
    }
}

// ---------------- 3. fold invden into h (32B per thread, MLP=2), reset denom ----------
__global__ void scale_kernel(int n) {
    int i = blockIdx.x * blockDim.x + threadIdx.x;   // n*8 threads
    if (i >= n * 8) return;
    int node = i >> 3;
    int head = (i >> 1) & 3;
    float den = g_denom[node * 4 + head];
    float inv = 1.0f / (den + 1e-16f);
    uint4* p = (uint4*)g_h16 + (size_t)i * 2;
    uint4 a = p[0];
    uint4 b = p[1];
    __half2* ha = (__half2*)&a;
    __half2* hb = (__half2*)&b;
#pragma unroll
    for (int q = 0; q < 4; q++) {
        float2 fa = __half22float2(ha[q]);
        float2 fb = __half22float2(hb[q]);
        ha[q] = __floats2half2_rn(fa.x * inv, fa.y * inv);
        hb[q] = __floats2half2_rn(fb.x * inv, fb.y * inv);
    }
    p[0] = a;
    p[1] = b;
    if ((i & 1) == 0) g_denom[node * 4 + head] = 0.0f;
}

// ---------------- 4. aggregate: smem-staged buckets, scalar LDS, f32x2 FMA ----------
__global__ __launch_bounds__(128, 10)
void agg_kernel(const float* __restrict__ bias, float* __restrict__ out, int n) {
    __shared__ uint4 s_bkt[8][CAP];                  // 8 KB
    int wslot = threadIdx.x >> 5;
    int lane = threadIdx.x & 31;
    int hl = lane & 15;
    int half = lane >> 4;
    int node = (blockIdx.x * 4 + wslot) * 2 + half;
    bool nvalid = node < n;
    int nodec = nvalid ? node : 0;

    int mycnt = nvalid ? g_cnt[nodec] : 0;
    if (mycnt > CAP) mycnt = CAP;
    int othercnt = __shfl_xor_sync(0xffffffffu, mycnt, 16);
    int maxcnt = mycnt > othercnt ? mycnt : othercnt;
    int base = nodec << 6;

    uint4* sb = s_bkt[wslot * 2 + half];
    for (int k = hl; k < maxcnt; k += 16)
        sb[k] = g_bkt[base + k];
    __syncwarp(0xffffffffu);

    int head = hl >> 2;
    bool hiHalf = head & 1;
    const uint32_t* sw = (const uint32_t*)sb;
    int woff = 1 + (head >> 1);

    unsigned long long acc64[4];
#pragma unroll
    for (int q = 0; q < 4; q++)
        asm("mov.b64 %0, {%1, %2};" : "=l"(acc64[q]) : "f"(0.0f), "f"(0.0f));

#pragma unroll 4
    for (int j = 0; j < maxcnt; j++) {
        bool live = j < mycnt;
        int sv = (int)sw[j * 4];
        uint32_t wp = sw[j * 4 + woff];
        int s = live ? sv : 0;
        __half2 wh2 = *(__half2*)&wp;
        float w = hiHalf ? __high2float(wh2) : __low2float(wh2);
        if (!live) w = 0.0f;
        unsigned long long w64;
        asm("mov.b64 %0, {%1, %1};" : "=l"(w64) : "f"(w));
        uint4 raw = *(const uint4*)(g_h16 + (size_t)s * HC + hl * 8);
        __half2* rh = (__half2*)&raw;
#pragma unroll
        for (int q = 0; q < 4; q++) {
            float2 f = __half22float2(rh[q]);
            unsigned long long h64;
            asm("mov.b64 %0, {%1, %2};" : "=l"(h64) : "f"(f.x), "f"(f.y));
            asm("fma.rn.f32x2 %0, %1, %2, %0;" : "+l"(acc64[q]) : "l"(h64), "l"(w64));
        }
    }

    if (nvalid) {
        float accv[8];
#pragma unroll
        for (int q = 0; q < 4; q++)
            asm("mov.b64 {%0, %1}, %2;" : "=f"(accv[q*2]), "=f"(accv[q*2+1]) : "l"(acc64[q]));
        float4 b0 = *(const float4*)(bias + hl * 8);
        float4 b1 = *(const float4*)(bias + hl * 8 + 4);
        float4 o0 = make_float4(accv[0] + b0.x, accv[1] + b0.y, accv[2] + b0.z, accv[3] + b0.w);
        float4 o1 = make_float4(accv[4] + b1.x, accv[5] + b1.y, accv[6] + b1.z, accv[7] + b1.w);
        *(float4*)(out + (size_t)node * HC + hl * 8)     = o0;
        *(float4*)(out + (size_t)node * HC + hl * 8 + 4) = o1;
        if (hl == 0) g_cnt[node] = 0;
    }
}

// ---------------- launch ----------------
extern "C" void kernel_launch(void* const* d_in, const int* in_sizes, int n_in,
                              void* d_out, int out_size) {
    const float* x    = (const float*)d_in[0];
    const float* w    = (const float*)d_in[1];
    const float* att  = (const float*)d_in[2];
    const float* bias = (const float*)d_in[3];
    const int*   ei   = (const int*)d_in[4];
    float* out = (float*)d_out;

    int n  = in_sizes[0] / INF;
    int E  = in_sizes[4] / 2;
    int Et = E + n;
    int halfT = (Et + 1) / 2;

    mma_gemm_kernel<<<(n + GBM - 1) / GBM, 256>>>(x, w, att, n);
    edge_kernel<<<(halfT + 255) / 256, 256>>>(ei, E, Et, halfT);
    scale_kernel<<<(n * 8 + 255) / 256, 256>>>(n);
    agg_kernel<<<(n + 7) / 8, 128>>>(bias, out, n);
}

// round 15
// speedup vs baseline: 1.0440x; 1.0440x over previous
#include <cuda_runtime.h>
#include <cuda_fp16.h>
#include <cstdint>

#define NN 50000
#define EE 800000
#define HC 128
#define INF 256
#define CAP 64            // bucket capacity per node (Poisson(17) tail @64 ~ 1e-16)

// ---------------- static device scratch ----------------
__device__ __align__(16) __half g_h16[(size_t)NN * HC];      // 12.8 MB (h, then h*invden)
__device__ __align__(16) float g_al[NN * 4];
__device__ __align__(16) float g_ar[NN * 4];
__device__ __align__(16) float g_denom[NN * 4];              // self-resetting
__device__ int   g_cnt[NN];                                  // self-resetting
__device__ __align__(16) uint4 g_bkt[(size_t)NN * CAP];      // {src, h2(e0,e1), h2(e2,e3), 0}

__device__ __forceinline__ float lrelu(float a) {
    return a > 0.0f ? a : 0.2f * a;
}
__device__ __forceinline__ uint32_t packh2(float a, float b) {
    __half2 h = __floats2half2_rn(a, b);
    return *(uint32_t*)&h;
}

// ---------------- 1. fp16 MMA GEMM (m16n8k16), reg double-buffer (round-13 form) ----
#define GBM 128
#define GBK 32
#define ASTRIDE 20
#define BSTRIDE 136
__global__ __launch_bounds__(256, 2)
void mma_gemm_kernel(const float* __restrict__ X, const float* __restrict__ W,
                     const float* __restrict__ att, int n) {
    __shared__ uint32_t Ash[GBM * ASTRIDE];      // 10.2 KB
    __shared__ uint32_t Bsh[16 * BSTRIDE];       // 8.7 KB
    __shared__ float s_att[256];
    int t = threadIdx.x;
    int lane = t & 31, warp = t >> 5;
    int grp = lane >> 2;
    int tig = lane & 3;
    int wm = (warp & 3) * 32;
    int wn = (warp >> 2) * 64;
    int rowbase = blockIdx.x * GBM;

    if (t < 256) s_att[t] = att[t];

    float acc[2][8][4];
#pragma unroll
    for (int ms = 0; ms < 2; ms++)
#pragma unroll
        for (int ns = 0; ns < 8; ns++)
#pragma unroll
            for (int q = 0; q < 4; q++) acc[ms][ns][q] = 0.0f;

    const int a_row = t >> 3;
    const int a_kq  = (t & 7) * 4;
    const int kq2   = (t & 7) * 2;
    const int b_kk  = t >> 5;
    const int b_nq  = (t & 31) * 4;

    float4 av[4], bv0[2], bv1[2];
#pragma unroll
    for (int i = 0; i < 4; i++) {
        int gr = rowbase + a_row + i * 32;
        av[i] = (gr < n) ? *(const float4*)(X + (size_t)gr * INF + a_kq)
                         : make_float4(0.f, 0.f, 0.f, 0.f);
    }
#pragma unroll
    for (int i = 0; i < 2; i++) {
        int kk = b_kk + i * 8;
        bv0[i] = *(const float4*)(W + (size_t)(2 * kk)     * HC + b_nq);
        bv1[i] = *(const float4*)(W + (size_t)(2 * kk + 1) * HC + b_nq);
    }

    for (int kb = 0; kb < INF; kb += GBK) {
#pragma unroll
        for (int i = 0; i < 4; i++) {
            int m = a_row + i * 32;
            uint2 p;
            p.x = packh2(av[i].x, av[i].y);
            p.y = packh2(av[i].z, av[i].w);
            *(uint2*)&Ash[m * ASTRIDE + kq2] = p;
        }
#pragma unroll
        for (int i = 0; i < 2; i++) {
            int kk = b_kk + i * 8;
            uint4 pk;
            pk.x = packh2(bv0[i].x, bv1[i].x);
            pk.y = packh2(bv0[i].y, bv1[i].y);
            pk.z = packh2(bv0[i].z, bv1[i].z);
            pk.w = packh2(bv0[i].w, bv1[i].w);
            *(uint4*)&Bsh[kk * BSTRIDE + b_nq] = pk;
        }
        __syncthreads();
        if (kb + GBK < INF) {
#pragma unroll
            for (int i = 0; i < 4; i++) {
                int gr = rowbase + a_row + i * 32;
                av[i] = (gr < n) ? *(const float4*)(X + (size_t)gr * INF + kb + GBK + a_kq)
                                 : make_float4(0.f, 0.f, 0.f, 0.f);
            }
#pragma unroll
            for (int i = 0; i < 2; i++) {
                int kk = b_kk + i * 8;
                bv0[i] = *(const float4*)(W + (size_t)(kb + GBK + 2 * kk)     * HC + b_nq);
                bv1[i] = *(const float4*)(W + (size_t)(kb + GBK + 2 * kk + 1) * HC + b_nq);
            }
        }
#pragma unroll
        for (int c = 0; c < 2; c++) {
            int kkb = c * 8 + tig;
            uint32_t a[2][4];
#pragma unroll
            for (int ms = 0; ms < 2; ms++) {
                int r = wm + ms * 16 + grp;
                a[ms][0] = Ash[r * ASTRIDE + kkb];
                a[ms][1] = Ash[(r + 8) * ASTRIDE + kkb];
                a[ms][2] = Ash[r * ASTRIDE + kkb + 4];
                a[ms][3] = Ash[(r + 8) * ASTRIDE + kkb + 4];
            }
#pragma unroll
            for (int ns = 0; ns < 8; ns++) {
                int cidx = wn + ns * 8 + grp;
                uint32_t b0 = Bsh[kkb * BSTRIDE + cidx];
                uint32_t b1 = Bsh[(kkb + 4) * BSTRIDE + cidx];
#pragma unroll
                for (int ms = 0; ms < 2; ms++) {
                    asm volatile(
                        "mma.sync.aligned.m16n8k16.row.col.f32.f16.f16.f32 "
                        "{%0,%1,%2,%3}, {%4,%5,%6,%7}, {%8,%9}, {%0,%1,%2,%3};"
                        : "+f"(acc[ms][ns][0]), "+f"(acc[ms][ns][1]),
                          "+f"(acc[ms][ns][2]), "+f"(acc[ms][ns][3])
                        : "r"(a[ms][0]), "r"(a[ms][1]), "r"(a[ms][2]), "r"(a[ms][3]),
                          "r"(b0), "r"(b1));
                }
            }
        }
        __syncthreads();
    }

    // ---- store h fragments as fp16 ----
#pragma unroll
    for (int ms = 0; ms < 2; ms++) {
#pragma unroll
        for (int ns = 0; ns < 8; ns++) {
            int r = rowbase + wm + ms * 16 + grp;
            int c = wn + ns * 8 + tig * 2;
            if (r < n)
                *(__half2*)(g_h16 + (size_t)r * HC + c) =
                    __floats2half2_rn(acc[ms][ns][0], acc[ms][ns][1]);
            if (r + 8 < n)
                *(__half2*)(g_h16 + (size_t)(r + 8) * HC + c) =
                    __floats2half2_rn(acc[ms][ns][2], acc[ms][ns][3]);
        }
    }

    // ---- fused attention dots ----
    float pal[4][2], par[4][2];
#pragma unroll
    for (int i = 0; i < 4; i++) { pal[i][0]=pal[i][1]=par[i][0]=par[i][1]=0.f; }
#pragma unroll
    for (int ns = 0; ns < 8; ns++) {
        int hs = ns >> 2;
        int c = wn + ns * 8 + tig * 2;
        int hd = c >> 5;
        int ci = c & 31;
        float wl0 = s_att[hd * 64 + ci],      wl1 = s_att[hd * 64 + ci + 1];
        float wr0 = s_att[hd * 64 + 32 + ci], wr1 = s_att[hd * 64 + 32 + ci + 1];
#pragma unroll
        for (int ms = 0; ms < 2; ms++) {
            pal[ms*2+0][hs] += acc[ms][ns][0]*wl0 + acc[ms][ns][1]*wl1;
            par[ms*2+0][hs] += acc[ms][ns][0]*wr0 + acc[ms][ns][1]*wr1;
            pal[ms*2+1][hs] += acc[ms][ns][2]*wl0 + acc[ms][ns][3]*wl1;
            par[ms*2+1][hs] += acc[ms][ns][2]*wr0 + acc[ms][ns][3]*wr1;
        }
    }
#pragma unroll
    for (int i = 0; i < 4; i++)
#pragma unroll
        for (int hs = 0; hs < 2; hs++) {
            pal[i][hs] += __shfl_xor_sync(0xffffffffu, pal[i][hs], 1);
            pal[i][hs] += __shfl_xor_sync(0xffffffffu, pal[i][hs], 2);
            par[i][hs] += __shfl_xor_sync(0xffffffffu, par[i][hs], 1);
            par[i][hs] += __shfl_xor_sync(0xffffffffu, par[i][hs], 2);
        }
    if (tig == 0) {
        int headbase = wn >> 5;
#pragma unroll
        for (int i = 0; i < 4; i++) {
            int r = rowbase + wm + (i >> 1) * 16 + grp + (i & 1) * 8;
            if (r < n) {
#pragma unroll
                for (int hs = 0; hs < 2; hs++) {
                    g_al[r * 4 + headbase + hs] = pal[i][hs];
                    g_ar[r * 4 + headbase + hs] = par[i][hs];
                }
            }
        }
    }
}

// ---------------- 2. fused edge pass: 2 adjacent edges/thread (MLP=2 chains) -------
__global__ void edge_kernel(const int* __restrict__ ei, int E, int Et, int halfT) {
    int t = blockIdx.x * blockDim.x + threadIdx.x;
    if (t >= halfT) return;
    int e0 = 2 * t, e1 = 2 * t + 1;
    bool has1 = e1 < Et;

    int s0, d0, s1 = 0, d1 = 0;
    if (e0 < E) { s0 = __ldg(ei + e0); d0 = __ldg(ei + E + e0); }
    else        { s0 = d0 = e0 - E; }
    if (has1) {
        if (e1 < E) { s1 = __ldg(ei + e1); d1 = __ldg(ei + E + e1); }
        else        { s1 = d1 = e1 - E; }
    }

    float4 alv0 = *(const float4*)(g_al + d0 * 4);
    float4 arv0 = *(const float4*)(g_ar + s0 * 4);
    float4 alv1, arv1;
    if (has1) {
        alv1 = *(const float4*)(g_al + d1 * 4);
        arv1 = *(const float4*)(g_ar + s1 * 4);
    }

    float a0 = __expf(lrelu(alv0.x + arv0.x));
    float a1 = __expf(lrelu(alv0.y + arv0.y));
    float a2 = __expf(lrelu(alv0.z + arv0.z));
    float a3 = __expf(lrelu(alv0.w + arv0.w));
    asm volatile("red.global.add.v4.f32 [%0], {%1,%2,%3,%4};"
                 :: "l"(g_denom + s0 * 4), "f"(a0), "f"(a1), "f"(a2), "f"(a3)
                 : "memory");
    float b0, b1, b2, b3;
    if (has1) {
        b0 = __expf(lrelu(alv1.x + arv1.x));
        b1 = __expf(lrelu(alv1.y + arv1.y));
        b2 = __expf(lrelu(alv1.z + arv1.z));
        b3 = __expf(lrelu(alv1.w + arv1.w));
        asm volatile("red.global.add.v4.f32 [%0], {%1,%2,%3,%4};"
                     :: "l"(g_denom + s1 * 4), "f"(b0), "f"(b1), "f"(b2), "f"(b3)
                     : "memory");
    }

    int p0 = atomicAdd(&g_cnt[d0], 1);
    int p1 = has1 ? atomicAdd(&g_cnt[d1], 1) : CAP;
    if (p0 < CAP) {
        uint4 v;
        v.x = (uint32_t)s0;
        v.y = packh2(a0, a1);
        v.z = packh2(a2, a3);
        v.w = 0;
        g_bkt[(d0 << 6) + p0] = v;
    }
    if (has1 && p1 < CAP) {
        uint4 v;
        v.x = (uint32_t)s1;
        v.y = packh2(b0, b1);
        v.z = packh2(b2, b3);
        v.w = 0;
        g_bkt[(d1 << 6) + p1] = v;
    }
}

// ---------------- 3. fold invden into h: one thread per (node,head), 64B, MLP=4 ----
__global__ void scale_kernel(int n) {
    int i = blockIdx.x * blockDim.x + threadIdx.x;   // n*4 threads
    if (i >= n * 4) return;
    float den = g_denom[i];
    float inv = 1.0f / (den + 1e-16f);
    g_denom[i] = 0.0f;                               // reset for next launch
    uint4* p = (uint4*)g_h16 + (size_t)i * 4;        // 64B = this head's 32 halves
    uint4 r0 = p[0], r1 = p[1], r2 = p[2], r3 = p[3];
    uint4* regs[4] = {&r0, &r1, &r2, &r3};
#pragma unroll
    for (int b = 0; b < 4; b++) {
        __half2* h2 = (__half2*)regs[b];
#pragma unroll
        for (int q = 0; q < 4; q++) {
            float2 f = __half22float2(h2[q]);
            h2[q] = __floats2half2_rn(f.x * inv, f.y * inv);
        }
    }
    p[0] = r0; p[1] = r1; p[2] = r2; p[3] = r3;
}

// ---------------- 4. aggregate: smem-staged buckets, scalar LDS, f32x2 FMA ----------
__global__ __launch_bounds__(128, 10)
void agg_kernel(const float* __restrict__ bias, float* __restrict__ out, int n) {
    __shared__ uint4 s_bkt[8][CAP];                  // 8 KB
    int wslot = threadIdx.x >> 5;
    int lane = threadIdx.x & 31;
    int hl = lane & 15;
    int half = lane >> 4;
    int node = (blockIdx.x * 4 + wslot) * 2 + half;
    bool nvalid = node < n;
    int nodec = nvalid ? node : 0;

    int mycnt = nvalid ? g_cnt[nodec] : 0;
    if (mycnt > CAP) mycnt = CAP;
    int othercnt = __shfl_xor_sync(0xffffffffu, mycnt, 16);
    int maxcnt = mycnt > othercnt ? mycnt : othercnt;
    int base = nodec << 6;

    uint4* sb = s_bkt[wslot * 2 + half];
    for (int k = hl; k < maxcnt; k += 16)
        sb[k] = g_bkt[base + k];
    __syncwarp(0xffffffffu);

    int head = hl >> 2;
    bool hiHalf = head & 1;
    const uint32_t* sw = (const uint32_t*)sb;
    int woff = 1 + (head >> 1);

    unsigned long long acc64[4];
#pragma unroll
    for (int q = 0; q < 4; q++)
        asm("mov.b64 %0, {%1, %2};" : "=l"(acc64[q]) : "f"(0.0f), "f"(0.0f));

#pragma unroll 4
    for (int j = 0; j < maxcnt; j++) {
        bool live = j < mycnt;
        int sv = (int)sw[j * 4];
        uint32_t wp = sw[j * 4 + woff];
        int s = live ? sv : 0;
        __half2 wh2 = *(__half2*)&wp;
        float w = hiHalf ? __high2float(wh2) : __low2float(wh2);
        if (!live) w = 0.0f;
        unsigned long long w64;
        asm("mov.b64 %0, {%1, %1};" : "=l"(w64) : "f"(w));
        uint4 raw = *(const uint4*)(g_h16 + (size_t)s * HC + hl * 8);
        __half2* rh = (__half2*)&raw;
#pragma unroll
        for (int q = 0; q < 4; q++) {
            float2 f = __half22float2(rh[q]);
            unsigned long long h64;
            asm("mov.b64 %0, {%1, %2};" : "=l"(h64) : "f"(f.x), "f"(f.y));
            asm("fma.rn.f32x2 %0, %1, %2, %0;" : "+l"(acc64[q]) : "l"(h64), "l"(w64));
        }
    }

    if (nvalid) {
        float accv[8];
#pragma unroll
        for (int q = 0; q < 4; q++)
            asm("mov.b64 {%0, %1}, %2;" : "=f"(accv[q*2]), "=f"(accv[q*2+1]) : "l"(acc64[q]));
        float4 b0 = *(const float4*)(bias + hl * 8);
        float4 b1 = *(const float4*)(bias + hl * 8 + 4);
        float4 o0 = make_float4(accv[0] + b0.x, accv[1] + b0.y, accv[2] + b0.z, accv[3] + b0.w);
        float4 o1 = make_float4(accv[4] + b1.x, accv[5] + b1.y, accv[6] + b1.z, accv[7] + b1.w);
        *(float4*)(out + (size_t)node * HC + hl * 8)     = o0;
        *(float4*)(out + (size_t)node * HC + hl * 8 + 4) = o1;
        if (hl == 0) g_cnt[node] = 0;
    }
}

// ---------------- launch ----------------
extern "C" void kernel_launch(void* const* d_in, const int* in_sizes, int n_in,
                              void* d_out, int out_size) {
    const float* x    = (const float*)d_in[0];
    const float* w    = (const float*)d_in[1];
    const float* att  = (const float*)d_in[2];
    const float* bias = (const float*)d_in[3];
    const int*   ei   = (const int*)d_in[4];
    float* out = (float*)d_out;

    int n  = in_sizes[0] / INF;
    int E  = in_sizes[4] / 2;
    int Et = E + n;
    int halfT = (Et + 1) / 2;

    mma_gemm_kernel<<<(n + GBM - 1) / GBM, 256>>>(x, w, att, n);
    edge_kernel<<<(halfT + 255) / 256, 256>>>(ei, E, Et, halfT);
    scale_kernel<<<(n * 4 + 255) / 256, 256>>>(n);
    agg_kernel<<<(n + 7) / 8, 128>>>(bias, out, n);
}

// round 16
// speedup vs baseline: 1.0752x; 1.0298x over previous
#include <cuda_runtime.h>
#include <cuda_fp16.h>
#include <cstdint>

#define NN 50000
#define EE 800000
#define HC 128
#define INF 256
#define CAP 64            // bucket capacity per node (Poisson(17) tail @64 ~ 1e-16)

// ---------------- static device scratch ----------------
__device__ __align__(16) __half g_h16[(size_t)NN * HC];      // 12.8 MB (h, then h*invden)
__device__ __align__(16) float g_al[NN * 4];
__device__ __align__(16) float g_ar[NN * 4];
__device__ __align__(16) float g_denom[NN * 4];              // self-resetting
__device__ int   g_cnt[NN];                                  // self-resetting
__device__ __align__(16) uint4 g_bkt[(size_t)NN * CAP];      // {src, h2(e0,e1), h2(e2,e3), 0}

__device__ __forceinline__ float lrelu(float a) {
    return a > 0.0f ? a : 0.2f * a;
}
__device__ __forceinline__ uint32_t packh2(float a, float b) {
    __half2 h = __floats2half2_rn(a, b);
    return *(uint32_t*)&h;
}

// ---------------- 1. fp16 MMA GEMM (m16n8k16), reg double-buffer, A via ldmatrix ----
#define GBM 128
#define GBK 32
#define ASTRIDE 20
#define BSTRIDE 136
__global__ __launch_bounds__(256, 2)
void mma_gemm_kernel(const float* __restrict__ X, const float* __restrict__ W,
                     const float* __restrict__ att, int n) {
    __shared__ uint32_t Ash[GBM * ASTRIDE];      // 10.2 KB
    __shared__ uint32_t Bsh[16 * BSTRIDE];       // 8.7 KB
    __shared__ float s_att[256];
    int t = threadIdx.x;
    int lane = t & 31, warp = t >> 5;
    int grp = lane >> 2;
    int tig = lane & 3;
    int wm = (warp & 3) * 32;
    int wn = (warp >> 2) * 64;
    int rowbase = blockIdx.x * GBM;

    if (t < 256) s_att[t] = att[t];

    float acc[2][8][4];
#pragma unroll
    for (int ms = 0; ms < 2; ms++)
#pragma unroll
        for (int ns = 0; ns < 8; ns++)
#pragma unroll
            for (int q = 0; q < 4; q++) acc[ms][ns][q] = 0.0f;

    const int a_row = t >> 3;
    const int a_kq  = (t & 7) * 4;
    const int kq2   = (t & 7) * 2;
    const int b_kk  = t >> 5;
    const int b_nq  = (t & 31) * 4;

    // ldmatrix lane address components: matrix i = lane>>3, row j = lane&7
    // matrix i: row offset (i&1)*8, word-col offset (i>>1)*4
    const int lm_i = lane >> 3;
    const int lm_j = lane & 7;
    const int lm_roff = (lm_i & 1) * 8 + lm_j;
    const int lm_coff = (lm_i >> 1) * 4;

    float4 av[4], bv0[2], bv1[2];
#pragma unroll
    for (int i = 0; i < 4; i++) {
        int gr = rowbase + a_row + i * 32;
        av[i] = (gr < n) ? *(const float4*)(X + (size_t)gr * INF + a_kq)
                         : make_float4(0.f, 0.f, 0.f, 0.f);
    }
#pragma unroll
    for (int i = 0; i < 2; i++) {
        int kk = b_kk + i * 8;
        bv0[i] = *(const float4*)(W + (size_t)(2 * kk)     * HC + b_nq);
        bv1[i] = *(const float4*)(W + (size_t)(2 * kk + 1) * HC + b_nq);
    }

    for (int kb = 0; kb < INF; kb += GBK) {
#pragma unroll
        for (int i = 0; i < 4; i++) {
            int m = a_row + i * 32;
            uint2 p;
            p.x = packh2(av[i].x, av[i].y);
            p.y = packh2(av[i].z, av[i].w);
            *(uint2*)&Ash[m * ASTRIDE + kq2] = p;
        }
#pragma unroll
        for (int i = 0; i < 2; i++) {
            int kk = b_kk + i * 8;
            uint4 pk;
            pk.x = packh2(bv0[i].x, bv1[i].x);
            pk.y = packh2(bv0[i].y, bv1[i].y);
            pk.z = packh2(bv0[i].z, bv1[i].z);
            pk.w = packh2(bv0[i].w, bv1[i].w);
            *(uint4*)&Bsh[kk * BSTRIDE + b_nq] = pk;
        }
        __syncthreads();
        if (kb + GBK < INF) {
#pragma unroll
            for (int i = 0; i < 4; i++) {
                int gr = rowbase + a_row + i * 32;
                av[i] = (gr < n) ? *(const float4*)(X + (size_t)gr * INF + kb + GBK + a_kq)
                                 : make_float4(0.f, 0.f, 0.f, 0.f);
            }
#pragma unroll
            for (int i = 0; i < 2; i++) {
                int kk = b_kk + i * 8;
                bv0[i] = *(const float4*)(W + (size_t)(kb + GBK + 2 * kk)     * HC + b_nq);
                bv1[i] = *(const float4*)(W + (size_t)(kb + GBK + 2 * kk + 1) * HC + b_nq);
            }
        }
#pragma unroll
        for (int c = 0; c < 2; c++) {
            int kkb = c * 8 + tig;
            uint32_t a[2][4];
#pragma unroll
            for (int ms = 0; ms < 2; ms++) {
                // one ldmatrix.x4 replaces 4 scalar LDS: matrices
                // {rows wm+ms*16(+8), word-cols c*8(+4)}
                uint32_t saddr = (uint32_t)__cvta_generic_to_shared(
                    &Ash[(wm + ms * 16 + lm_roff) * ASTRIDE + c * 8 + lm_coff]);
                asm volatile(
                    "ldmatrix.sync.aligned.m8n8.x4.shared.b16 {%0,%1,%2,%3}, [%4];"
                    : "=r"(a[ms][0]), "=r"(a[ms][1]), "=r"(a[ms][2]), "=r"(a[ms][3])
                    : "r"(saddr));
            }
#pragma unroll
            for (int ns = 0; ns < 8; ns++) {
                int cidx = wn + ns * 8 + grp;
                uint32_t b0 = Bsh[kkb * BSTRIDE + cidx];
                uint32_t b1 = Bsh[(kkb + 4) * BSTRIDE + cidx];
#pragma unroll
                for (int ms = 0; ms < 2; ms++) {
                    asm volatile(
                        "mma.sync.aligned.m16n8k16.row.col.f32.f16.f16.f32 "
                        "{%0,%1,%2,%3}, {%4,%5,%6,%7}, {%8,%9}, {%0,%1,%2,%3};"
                        : "+f"(acc[ms][ns][0]), "+f"(acc[ms][ns][1]),
                          "+f"(acc[ms][ns][2]), "+f"(acc[ms][ns][3])
                        : "r"(a[ms][0]), "r"(a[ms][1]), "r"(a[ms][2]), "r"(a[ms][3]),
                          "r"(b0), "r"(b1));
                }
            }
        }
        __syncthreads();
    }

    // ---- store h fragments as fp16 ----
#pragma unroll
    for (int ms = 0; ms < 2; ms++) {
#pragma unroll
        for (int ns = 0; ns < 8; ns++) {
            int r = rowbase + wm + ms * 16 + grp;
            int c = wn + ns * 8 + tig * 2;
            if (r < n)
                *(__half2*)(g_h16 + (size_t)r * HC + c) =
                    __floats2half2_rn(acc[ms][ns][0], acc[ms][ns][1]);
            if (r + 8 < n)
                *(__half2*)(g_h16 + (size_t)(r + 8) * HC + c) =
                    __floats2half2_rn(acc[ms][ns][2], acc[ms][ns][3]);
        }
    }

    // ---- fused attention dots ----
    float pal[4][2], par[4][2];
#pragma unroll
    for (int i = 0; i < 4; i++) { pal[i][0]=pal[i][1]=par[i][0]=par[i][1]=0.f; }
#pragma unroll
    for (int ns = 0; ns < 8; ns++) {
        int hs = ns >> 2;
        int c = wn + ns * 8 + tig * 2;
        int hd = c >> 5;
        int ci = c & 31;
        float wl0 = s_att[hd * 64 + ci],      wl1 = s_att[hd * 64 + ci + 1];
        float wr0 = s_att[hd * 64 + 32 + ci], wr1 = s_att[hd * 64 + 32 + ci + 1];
#pragma unroll
        for (int ms = 0; ms < 2; ms++) {
            pal[ms*2+0][hs] += acc[ms][ns][0]*wl0 + acc[ms][ns][1]*wl1;
            par[ms*2+0][hs] += acc[ms][ns][0]*wr0 + acc[ms][ns][1]*wr1;
            pal[ms*2+1][hs] += acc[ms][ns][2]*wl0 + acc[ms][ns][3]*wl1;
            par[ms*2+1][hs] += acc[ms][ns][2]*wr0 + acc[ms][ns][3]*wr1;
        }
    }
#pragma unroll
    for (int i = 0; i < 4; i++)
#pragma unroll
        for (int hs = 0; hs < 2; hs++) {
            pal[i][hs] += __shfl_xor_sync(0xffffffffu, pal[i][hs], 1);
            pal[i][hs] += __shfl_xor_sync(0xffffffffu, pal[i][hs], 2);
            par[i][hs] += __shfl_xor_sync(0xffffffffu, par[i][hs], 1);
            par[i][hs] += __shfl_xor_sync(0xffffffffu, par[i][hs], 2);
        }
    if (tig == 0) {
        int headbase = wn >> 5;
#pragma unroll
        for (int i = 0; i < 4; i++) {
            int r = rowbase + wm + (i >> 1) * 16 + grp + (i & 1) * 8;
            if (r < n) {
#pragma unroll
                for (int hs = 0; hs < 2; hs++) {
                    g_al[r * 4 + headbase + hs] = pal[i][hs];
                    g_ar[r * 4 + headbase + hs] = par[i][hs];
                }
            }
        }
    }
}

// ---------------- 2. fused edge pass: exp + denom RED + packed bucket fill ----------
// (round-13 form: 1 edge/thread — measured best)
__global__ void edge_kernel(const int* __restrict__ ei, int E, int Et) {
    int e = blockIdx.x * blockDim.x + threadIdx.x;
    if (e >= Et) return;
    int src, dst;
    if (e < E) { src = __ldg(ei + e); dst = __ldg(ei + E + e); }
    else       { src = dst = e - E; }
    float4 alv = *(const float4*)(g_al + dst * 4);
    float4 arv = *(const float4*)(g_ar + src * 4);
    float e0 = __expf(lrelu(alv.x + arv.x));
    float e1 = __expf(lrelu(alv.y + arv.y));
    float e2 = __expf(lrelu(alv.z + arv.z));
    float e3 = __expf(lrelu(alv.w + arv.w));
    asm volatile("red.global.add.v4.f32 [%0], {%1,%2,%3,%4};"
                 :: "l"(g_denom + src * 4), "f"(e0), "f"(e1), "f"(e2), "f"(e3)
                 : "memory");
    int pos = atomicAdd(&g_cnt[dst], 1);
    if (pos < CAP) {
        uint4 v;
        v.x = (uint32_t)src;
        v.y = packh2(e0, e1);
        v.z = packh2(e2, e3);
        v.w = 0;
        g_bkt[(dst << 6) + pos] = v;
    }
}

// ---------------- 3. fold invden into h (32B per thread, MLP=2), reset denom ----------
// (round-13 form — measured best)
__global__ void scale_kernel(int n) {
    int i = blockIdx.x * blockDim.x + threadIdx.x;   // n*8 threads
    if (i >= n * 8) return;
    int node = i >> 3;
    int head = (i >> 1) & 3;
    float den = g_denom[node * 4 + head];
    float inv = 1.0f / (den + 1e-16f);
    uint4* p = (uint4*)g_h16 + (size_t)i * 2;
    uint4 a = p[0];
    uint4 b = p[1];
    __half2* ha = (__half2*)&a;
    __half2* hb = (__half2*)&b;
#pragma unroll
    for (int q = 0; q < 4; q++) {
        float2 fa = __half22float2(ha[q]);
        float2 fb = __half22float2(hb[q]);
        ha[q] = __floats2half2_rn(fa.x * inv, fa.y * inv);
        hb[q] = __floats2half2_rn(fb.x * inv, fb.y * inv);
    }
    p[0] = a;
    p[1] = b;
    if ((i & 1) == 0) g_denom[node * 4 + head] = 0.0f;
}

// ---------------- 4. aggregate: smem-staged buckets, scalar LDS, f32x2 FMA ----------
__global__ __launch_bounds__(128, 10)
void agg_kernel(const float* __restrict__ bias, float* __restrict__ out, int n) {
    __shared__ uint4 s_bkt[8][CAP];                  // 8 KB
    int wslot = threadIdx.x >> 5;
    int lane = threadIdx.x & 31;
    int hl = lane & 15;
    int half = lane >> 4;
    int node = (blockIdx.x * 4 + wslot) * 2 + half;
    bool nvalid = node < n;
    int nodec = nvalid ? node : 0;

    int mycnt = nvalid ? g_cnt[nodec] : 0;
    if (mycnt > CAP) mycnt = CAP;
    int othercnt = __shfl_xor_sync(0xffffffffu, mycnt, 16);
    int maxcnt = mycnt > othercnt ? mycnt : othercnt;
    int base = nodec << 6;

    uint4* sb = s_bkt[wslot * 2 + half];
    for (int k = hl; k < maxcnt; k += 16)
        sb[k] = g_bkt[base + k];
    __syncwarp(0xffffffffu);

    int head = hl >> 2;
    bool hiHalf = head & 1;
    const uint32_t* sw = (const uint32_t*)sb;
    int woff = 1 + (head >> 1);

    unsigned long long acc64[4];
#pragma unroll
    for (int q = 0; q < 4; q++)
        asm("mov.b64 %0, {%1, %2};" : "=l"(acc64[q]) : "f"(0.0f), "f"(0.0f));

#pragma unroll 4
    for (int j = 0; j < maxcnt; j++) {
        bool live = j < mycnt;
        int sv = (int)sw[j * 4];
        uint32_t wp = sw[j * 4 + woff];
        int s = live ? sv : 0;
        __half2 wh2 = *(__half2*)&wp;
        float w = hiHalf ? __high2float(wh2) : __low2float(wh2);
        if (!live) w = 0.0f;
        unsigned long long w64;
        asm("mov.b64 %0, {%1, %1};" : "=l"(w64) : "f"(w));
        uint4 raw = *(const uint4*)(g_h16 + (size_t)s * HC + hl * 8);
        __half2* rh = (__half2*)&raw;
#pragma unroll
        for (int q = 0; q < 4; q++) {
            float2 f = __half22float2(rh[q]);
            unsigned long long h64;
            asm("mov.b64 %0, {%1, %2};" : "=l"(h64) : "f"(f.x), "f"(f.y));
            asm("fma.rn.f32x2 %0, %1, %2, %0;" : "+l"(acc64[q]) : "l"(h64), "l"(w64));
        }
    }

    if (nvalid) {
        float accv[8];
#pragma unroll
        for (int q = 0; q < 4; q++)
            asm("mov.b64 {%0, %1}, %2;" : "=f"(accv[q*2]), "=f"(accv[q*2+1]) : "l"(acc64[q]));
        float4 b0 = *(const float4*)(bias + hl * 8);
        float4 b1 = *(const float4*)(bias + hl * 8 + 4);
        float4 o0 = make_float4(accv[0] + b0.x, accv[1] + b0.y, accv[2] + b0.z, accv[3] + b0.w);
        float4 o1 = make_float4(accv[4] + b1.x, accv[5] + b1.y, accv[6] + b1.z, accv[7] + b1.w);
        *(float4*)(out + (size_t)node * HC + hl * 8)     = o0;
        *(float4*)(out + (size_t)node * HC + hl * 8 + 4) = o1;
        if (hl == 0) g_cnt[node] = 0;
    }
}

// ---------------- launch ----------------
extern "C" void kernel_launch(void* const* d_in, const int* in_sizes, int n_in,
                              void* d_out, int out_size) {
    const float* x    = (const float*)d_in[0];
    const float* w    = (const float*)d_in[1];
    const float* att  = (const float*)d_in[2];
    const float* bias = (const float*)d_in[3];
    const int*   ei   = (const int*)d_in[4];
    float* out = (float*)d_out;

    int n  = in_sizes[0] / INF;
    int E  = in_sizes[4] / 2;
    int Et = E + n;

    mma_gemm_kernel<<<(n + GBM - 1) / GBM, 256>>>(x, w, att, n);
    edge_kernel<<<(Et + 255) / 256, 256>>>(ei, E, Et);
    scale_kernel<<<(n * 8 + 255) / 256, 256>>>(n);
    agg_kernel<<<(n + 7) / 8, 128>>>(bias, out, n);
}